// round 1
// baseline (speedup 1.0000x reference)
#include <cuda_runtime.h>
#include <cuda_bf16.h>
#include <math.h>

// ---------------- problem constants ----------------
#define RESO 56
#define WS   7
#define CDIM 128
#define NHEAD 4
#define HDIM 32
#define HID  512
#define BATCH 32
#define NTOK (BATCH * RESO * RESO)      // 100352
#define NWIN (BATCH * 8 * 8)            // 2048 windows
#define TWIN 49                         // tokens per window

// ---------------- device scratch (no allocation allowed) ----------------
__device__ float g_ln [(size_t)NTOK * CDIM];   // LN output (reused for LN1 and LN2)
__device__ float g_qkv[(size_t)NTOK * 3 * CDIM];
__device__ float g_o  [(size_t)NTOK * CDIM];   // attention output (token-major)
__device__ float g_x2 [(size_t)NTOK * CDIM];   // x + proj(o)
__device__ float g_h1 [(size_t)NTOK * HID];    // gelu(mlp1)

// ---------------- LayerNorm: one warp per token (C=128 -> float4/lane) -----
__global__ void ln_kernel(const float* __restrict__ x,
                          const float* __restrict__ g,
                          const float* __restrict__ b,
                          float* __restrict__ out)
{
    int gwarp = (blockIdx.x * blockDim.x + threadIdx.x) >> 5;
    int lane  = threadIdx.x & 31;
    if (gwarp >= NTOK) return;
    const float4* xr = (const float4*)(x + (size_t)gwarp * CDIM);
    float4 v = xr[lane];
    float s  = v.x + v.y + v.z + v.w;
    float ss = v.x*v.x + v.y*v.y + v.z*v.z + v.w*v.w;
    #pragma unroll
    for (int off = 16; off; off >>= 1) {
        s  += __shfl_xor_sync(0xffffffffu, s,  off);
        ss += __shfl_xor_sync(0xffffffffu, ss, off);
    }
    float mean = s * (1.0f / CDIM);
    float var  = ss * (1.0f / CDIM) - mean * mean;
    float rstd = rsqrtf(var + 1e-5f);
    float4 gg = ((const float4*)g)[lane];
    float4 bb = ((const float4*)b)[lane];
    float4 o;
    o.x = (v.x - mean) * rstd * gg.x + bb.x;
    o.y = (v.y - mean) * rstd * gg.y + bb.y;
    o.z = (v.z - mean) * rstd * gg.z + bb.z;
    o.w = (v.w - mean) * rstd * gg.w + bb.w;
    ((float4*)(out + (size_t)gwarp * CDIM))[lane] = o;
}

// ---------------- SGEMM: C[M,N] = A[M,K] @ W[K,N] (+bias)(+res)(gelu) ------
#define BM 128
#define BN 128
#define BK 8
enum { EPI_BIAS = 0, EPI_BIAS_RES = 1, EPI_GELU = 2 };

template <int EPI>
__global__ __launch_bounds__(256)
void sgemm_kernel(const float* __restrict__ A, const float* __restrict__ W,
                  const float* __restrict__ bias, const float* __restrict__ res,
                  float* __restrict__ C, int M, int N, int K)
{
    __shared__ float As[BK][BM];
    __shared__ float Bs[BK][BN];
    int tid = threadIdx.x;
    int bx = blockIdx.x, by = blockIdx.y;
    int ty = tid >> 4, tx = tid & 15;

    const float* Ab = A + (size_t)(by * BM) * K;
    const float* Wb = W + bx * BN;

    int aRow = tid >> 1;            // 0..127
    int aCol = (tid & 1) * 4;       // 0 or 4
    int bRow = tid >> 5;            // 0..7
    int bCol = (tid & 31) * 4;      // 0..124

    float acc[8][8];
    #pragma unroll
    for (int i = 0; i < 8; i++)
        #pragma unroll
        for (int j = 0; j < 8; j++) acc[i][j] = 0.0f;

    for (int k0 = 0; k0 < K; k0 += BK) {
        float4 av = *(const float4*)(Ab + (size_t)aRow * K + k0 + aCol);
        As[aCol + 0][aRow] = av.x;
        As[aCol + 1][aRow] = av.y;
        As[aCol + 2][aRow] = av.z;
        As[aCol + 3][aRow] = av.w;
        *(float4*)(&Bs[bRow][bCol]) =
            *(const float4*)(Wb + (size_t)(k0 + bRow) * N + bCol);
        __syncthreads();
        #pragma unroll
        for (int k = 0; k < BK; k++) {
            float af[8], bf[8];
            *(float4*)(af)     = *(const float4*)(&As[k][ty * 8]);
            *(float4*)(af + 4) = *(const float4*)(&As[k][ty * 8 + 4]);
            *(float4*)(bf)     = *(const float4*)(&Bs[k][tx * 8]);
            *(float4*)(bf + 4) = *(const float4*)(&Bs[k][tx * 8 + 4]);
            #pragma unroll
            for (int i = 0; i < 8; i++)
                #pragma unroll
                for (int j = 0; j < 8; j++)
                    acc[i][j] = fmaf(af[i], bf[j], acc[i][j]);
        }
        __syncthreads();
    }

    int row0 = by * BM + ty * 8;
    int col0 = bx * BN + tx * 8;
    float bs[8];
    #pragma unroll
    for (int j = 0; j < 8; j++) bs[j] = bias[col0 + j];

    #pragma unroll
    for (int i = 0; i < 8; i++) {
        size_t roff = (size_t)(row0 + i) * N + col0;
        float v[8];
        #pragma unroll
        for (int j = 0; j < 8; j++) {
            float t = acc[i][j] + bs[j];
            if (EPI == EPI_BIAS_RES) t += res[roff + j];
            if (EPI == EPI_GELU)
                t = 0.5f * t * (1.0f + erff(t * 0.70710678118654752f));
            v[j] = t;
        }
        *(float4*)(C + roff)     = *(float4*)(v);
        *(float4*)(C + roff + 4) = *(float4*)(v + 4);
    }
}

// ---------------- windowed attention: 1 block per (window, head) ----------
__global__ __launch_bounds__(256)
void attn_kernel(const float* __restrict__ qkv, float* __restrict__ o)
{
    int blk  = blockIdx.x;          // 0..NWIN*NHEAD-1
    int head = blk & 3;
    int w    = blk >> 2;
    int bimg = w >> 6;
    int win  = w & 63;
    int wr   = win >> 3, wc = win & 7;

    __shared__ int   tok[TWIN];
    __shared__ float qs[TWIN * 33];
    __shared__ float ks[TWIN * 33];
    __shared__ float vs[TWIN * 33];
    __shared__ float S[TWIN * TWIN];

    int tid = threadIdx.x;
    if (tid < TWIN) {
        int r = tid / WS, c = tid - r * WS;
        tok[tid] = bimg * (RESO * RESO) + (wr * WS + r) * RESO + (wc * WS + c);
    }
    __syncthreads();

    // load q,k,v slices for this head: 49 * 32 * 3 elements
    for (int idx = tid; idx < TWIN * HDIM * 3; idx += 256) {
        int which = idx / (TWIN * HDIM);
        int rem   = idx - which * (TWIN * HDIM);
        int t = rem >> 5, d = rem & 31;
        float val = qkv[(size_t)tok[t] * (3 * CDIM) + which * CDIM + head * HDIM + d];
        float* dst = (which == 0) ? qs : (which == 1) ? ks : vs;
        dst[t * 33 + d] = val;
    }
    __syncthreads();

    // S = q @ k^T * scale
    const float scale = 0.17677669529663687f;  // 1/sqrt(32)
    for (int idx = tid; idx < TWIN * TWIN; idx += 256) {
        int qi = idx / TWIN, ki = idx - qi * TWIN;
        float s = 0.0f;
        #pragma unroll
        for (int d = 0; d < HDIM; d++)
            s = fmaf(qs[qi * 33 + d], ks[ki * 33 + d], s);
        S[idx] = s * scale;
    }
    __syncthreads();

    // softmax per row (warp per row, lane covers col and col+32)
    int warp = tid >> 5, lane = tid & 31;
    for (int row = warp; row < TWIN; row += 8) {
        float v0 = S[row * TWIN + lane];
        float v1 = (lane + 32 < TWIN) ? S[row * TWIN + lane + 32] : -3.4e38f;
        float m = fmaxf(v0, v1);
        #pragma unroll
        for (int off = 16; off; off >>= 1)
            m = fmaxf(m, __shfl_xor_sync(0xffffffffu, m, off));
        float e0 = __expf(v0 - m);
        float e1 = (lane + 32 < TWIN) ? __expf(v1 - m) : 0.0f;
        float s = e0 + e1;
        #pragma unroll
        for (int off = 16; off; off >>= 1)
            s += __shfl_xor_sync(0xffffffffu, s, off);
        float inv = 1.0f / s;
        S[row * TWIN + lane] = e0 * inv;
        if (lane + 32 < TWIN) S[row * TWIN + lane + 32] = e1 * inv;
    }
    __syncthreads();

    // O = P @ V ; scatter back to token-major layout
    for (int idx = tid; idx < TWIN * HDIM; idx += 256) {
        int qi = idx >> 5, d = idx & 31;
        float acc = 0.0f;
        #pragma unroll
        for (int ki = 0; ki < TWIN; ki++)
            acc = fmaf(S[qi * TWIN + ki], vs[ki * 33 + d], acc);
        o[(size_t)tok[qi] * CDIM + head * HDIM + d] = acc;
    }
}

// ---------------- launch ----------------
extern "C" void kernel_launch(void* const* d_in, const int* in_sizes, int n_in,
                              void* d_out, int out_size)
{
    const float* x      = (const float*)d_in[0];
    const float* ln1_g  = (const float*)d_in[1];
    const float* ln1_b  = (const float*)d_in[2];
    const float* qkv_w  = (const float*)d_in[3];
    const float* qkv_b  = (const float*)d_in[4];
    const float* proj_w = (const float*)d_in[5];
    const float* proj_b = (const float*)d_in[6];
    const float* ln2_g  = (const float*)d_in[7];
    const float* ln2_b  = (const float*)d_in[8];
    const float* mlp_w1 = (const float*)d_in[9];
    const float* mlp_b1 = (const float*)d_in[10];
    const float* mlp_w2 = (const float*)d_in[11];
    const float* mlp_b2 = (const float*)d_in[12];
    float* out = (float*)d_out;

    float *p_ln, *p_qkv, *p_o, *p_x2, *p_h1;
    cudaGetSymbolAddress((void**)&p_ln,  g_ln);
    cudaGetSymbolAddress((void**)&p_qkv, g_qkv);
    cudaGetSymbolAddress((void**)&p_o,   g_o);
    cudaGetSymbolAddress((void**)&p_x2,  g_x2);
    cudaGetSymbolAddress((void**)&p_h1,  g_h1);

    const int M = NTOK;
    dim3 blk(256);

    // 1. LN1
    ln_kernel<<<(NTOK * 32) / 256, blk>>>(x, ln1_g, ln1_b, p_ln);
    // 2. QKV = ln1 @ qkv_w + qkv_b        [M,128]x[128,384]
    sgemm_kernel<EPI_BIAS><<<dim3(3, M / BM), blk>>>(
        p_ln, qkv_w, qkv_b, nullptr, p_qkv, M, 3 * CDIM, CDIM);
    // 3. windowed attention -> o (token-major)
    attn_kernel<<<NWIN * NHEAD, blk>>>(p_qkv, p_o);
    // 4. x2 = x + o @ proj_w + proj_b     [M,128]x[128,128]
    sgemm_kernel<EPI_BIAS_RES><<<dim3(1, M / BM), blk>>>(
        p_o, proj_w, proj_b, x, p_x2, M, CDIM, CDIM);
    // 5. LN2
    ln_kernel<<<(NTOK * 32) / 256, blk>>>(p_x2, ln2_g, ln2_b, p_ln);
    // 6. h1 = gelu(ln2 @ mlp_w1 + mlp_b1) [M,128]x[128,512]
    sgemm_kernel<EPI_GELU><<<dim3(HID / BN, M / BM), blk>>>(
        p_ln, mlp_w1, mlp_b1, nullptr, p_h1, M, HID, CDIM);
    // 7. out = x2 + h1 @ mlp_w2 + mlp_b2  [M,512]x[512,128]
    sgemm_kernel<EPI_BIAS_RES><<<dim3(1, M / BM), blk>>>(
        p_h1, mlp_w2, mlp_b2, p_x2, out, M, CDIM, HID);
}

// round 3
// speedup vs baseline: 1.3365x; 1.3365x over previous
#include <cuda_runtime.h>
#include <cuda_bf16.h>
#include <mma.h>
#include <math.h>
#include <stdint.h>

using namespace nvcuda;

// ---------------- problem constants ----------------
#define RESO 56
#define WS   7
#define CDIM 128
#define NHEAD 4
#define HDIM 32
#define HID  512
#define BATCH 32
#define NTOK (BATCH * RESO * RESO)      // 100352
#define NWIN (BATCH * 8 * 8)            // 2048 windows
#define TWIN 49

// ---------------- device scratch ----------------
__device__ float g_ln [(size_t)NTOK * CDIM];
__device__ float g_qkv[(size_t)NTOK * 3 * CDIM];
__device__ float g_o  [(size_t)NTOK * CDIM];
__device__ float g_x2 [(size_t)NTOK * CDIM];
__device__ float g_h1 [(size_t)NTOK * HID];
// tf32-rounded weights, same [K,N] layout: qkv(128x384) proj(128x128) w1(128x512) w2(512x128)
__device__ float g_wT [49152 + 16384 + 65536 + 65536];

__device__ __forceinline__ float f2tf32f(float f) {
    uint32_t r; asm("cvt.rna.tf32.f32 %0, %1;" : "=r"(r) : "f"(f));
    return __uint_as_float(r);
}
__device__ __forceinline__ uint32_t smem_u32(const void* p) {
    uint32_t a;
    asm("{ .reg .u64 t; cvta.to.shared.u64 t, %1; cvt.u32.u64 %0, t; }" : "=r"(a) : "l"(p));
    return a;
}
__device__ __forceinline__ void cp_async16(uint32_t saddr, const void* gaddr) {
    asm volatile("cp.async.ca.shared.global [%0], [%1], 16;" :: "r"(saddr), "l"(gaddr));
}
#define CP_COMMIT() asm volatile("cp.async.commit_group;" ::: "memory")
#define CP_WAIT(n)  asm volatile("cp.async.wait_group %0;" :: "n"(n) : "memory")

// ---------------- LayerNorm (tf32-rounded output) ----------------
__global__ void ln_kernel(const float* __restrict__ x, const float* __restrict__ g,
                          const float* __restrict__ b, float* __restrict__ out)
{
    int gwarp = (blockIdx.x * blockDim.x + threadIdx.x) >> 5;
    int lane  = threadIdx.x & 31;
    if (gwarp >= NTOK) return;
    float4 v = ((const float4*)(x + (size_t)gwarp * CDIM))[lane];
    float s  = v.x + v.y + v.z + v.w;
    float ss = v.x*v.x + v.y*v.y + v.z*v.z + v.w*v.w;
    #pragma unroll
    for (int off = 16; off; off >>= 1) {
        s  += __shfl_xor_sync(0xffffffffu, s,  off);
        ss += __shfl_xor_sync(0xffffffffu, ss, off);
    }
    float mean = s * (1.0f / CDIM);
    float var  = ss * (1.0f / CDIM) - mean * mean;
    float rstd = rsqrtf(var + 1e-5f);
    float4 gg = ((const float4*)g)[lane];
    float4 bb = ((const float4*)b)[lane];
    float4 o;
    o.x = f2tf32f((v.x - mean) * rstd * gg.x + bb.x);
    o.y = f2tf32f((v.y - mean) * rstd * gg.y + bb.y);
    o.z = f2tf32f((v.z - mean) * rstd * gg.z + bb.z);
    o.w = f2tf32f((v.w - mean) * rstd * gg.w + bb.w);
    ((float4*)(out + (size_t)gwarp * CDIM))[lane] = o;
}

// ---------------- weight rounding to tf32 (layout preserved) ----------------
__global__ void round_tf32(const float* __restrict__ W, float* __restrict__ WT, int n)
{
    int idx = blockIdx.x * 256 + threadIdx.x;
    if (idx < n) WT[idx] = f2tf32f(W[idx]);
}

// ---------------- WMMA tf32 GEMM: C[M,N] = A[M,K] @ B[K,N] -----------------
// CTA tile 128x128, 8 warps (2x4), warp tile 64x32 (4x2 of m16n16k8).
// K-chunks of 32, double-buffered cp.async. Inputs pre-rounded to tf32.
enum { EPI_BIAS = 0, EPI_BIAS_RES = 1, EPI_GELU = 2 };

#define A_STRIDE 36   // floats (144B)
#define B_STRIDE 136  // floats (544B)
#define C_STRIDE 132  // floats (528B)
#define ABUF (128 * A_STRIDE * 4)          // 18432 B
#define BBUF (32 * B_STRIDE * 4)           // 17408 B
#define SMEM_BYTES (2 * ABUF + 2 * BBUF)   // 71680 B (epilogue reuses this)

template <int EPI>
__global__ void __launch_bounds__(256, 2)
tc_gemm(const float* __restrict__ A, const float* __restrict__ B,
        const float* __restrict__ bias, const float* __restrict__ res,
        float* __restrict__ C, int N, int K)
{
    extern __shared__ char smem[];
    uint32_t sbase = smem_u32(smem);
    const int tid = threadIdx.x;
    const int wid = tid >> 5;
    const int warpM = wid & 1;          // 0..1
    const int warpN = wid >> 1;         // 0..3
    const int M0 = blockIdx.y * 128;
    const int N0 = blockIdx.x * 128;

    const float* Abase = A + (size_t)M0 * K;
    const float* Bbase = B + N0;
    const int nchunk = K >> 5;

    wmma::fragment<wmma::accumulator, 16, 16, 8, float> acc[4][2];
    #pragma unroll
    for (int i = 0; i < 4; i++)
        #pragma unroll
        for (int j = 0; j < 2; j++) wmma::fill_fragment(acc[i][j], 0.0f);

    // per-thread cp.async assignments (1024 16B-chunks each for A and B)
    // A: e in [tid*4, tid*4+4): row=e>>3, c16=e&7
    // B: e: row=e>>5, c16=e&31
    auto load_chunk = [&](int c) {
        int buf = c & 1;
        uint32_t sa = sbase + buf * ABUF;
        uint32_t sb = sbase + 2 * ABUF + buf * BBUF;
        int k0 = c << 5;
        #pragma unroll
        for (int q = 0; q < 4; q++) {
            int e = tid * 4 + q;
            int row = e >> 3, c16 = e & 7;
            cp_async16(sa + row * (A_STRIDE * 4) + c16 * 16,
                       Abase + (size_t)row * K + k0 + c16 * 4);
        }
        #pragma unroll
        for (int q = 0; q < 4; q++) {
            int e = tid * 4 + q;
            int row = e >> 5, c16 = e & 31;
            cp_async16(sb + row * (B_STRIDE * 4) + c16 * 16,
                       Bbase + (size_t)(k0 + row) * N + c16 * 4);
        }
    };

    load_chunk(0);
    CP_COMMIT();

    for (int c = 0; c < nchunk; c++) {
        if (c + 1 < nchunk) {
            load_chunk(c + 1);
            CP_COMMIT();
            CP_WAIT(1);
        } else {
            CP_WAIT(0);
        }
        __syncthreads();

        int buf = c & 1;
        const float* As = (const float*)(smem + buf * ABUF);
        const float* Bs = (const float*)(smem + 2 * ABUF + buf * BBUF);
        #pragma unroll
        for (int ks = 0; ks < 4; ks++) {
            wmma::fragment<wmma::matrix_a, 16, 16, 8, wmma::precision::tf32, wmma::row_major> af[4];
            wmma::fragment<wmma::matrix_b, 16, 16, 8, wmma::precision::tf32, wmma::row_major> bf[2];
            #pragma unroll
            for (int i = 0; i < 4; i++)
                wmma::load_matrix_sync(af[i],
                    As + (warpM * 64 + i * 16) * A_STRIDE + ks * 8, A_STRIDE);
            #pragma unroll
            for (int j = 0; j < 2; j++)
                wmma::load_matrix_sync(bf[j],
                    Bs + (ks * 8) * B_STRIDE + warpN * 32 + j * 16, B_STRIDE);
            #pragma unroll
            for (int i = 0; i < 4; i++)
                #pragma unroll
                for (int j = 0; j < 2; j++)
                    wmma::mma_sync(acc[i][j], af[i], bf[j], acc[i][j]);
        }
        __syncthreads();
    }

    // epilogue: stage accumulators in smem (reuse buffers), fuse bias/res/gelu
    float* Cs = (float*)smem;
    #pragma unroll
    for (int i = 0; i < 4; i++)
        #pragma unroll
        for (int j = 0; j < 2; j++)
            wmma::store_matrix_sync(
                Cs + (warpM * 64 + i * 16) * C_STRIDE + warpN * 32 + j * 16,
                acc[i][j], C_STRIDE, wmma::mem_row_major);
    __syncthreads();

    #pragma unroll
    for (int e0 = 0; e0 < 16; e0++) {
        int e = tid + e0 * 256;            // 0..4095 float4s
        int row = e >> 5;
        int c4  = (e & 31) * 4;
        size_t roff = (size_t)(M0 + row) * N + N0 + c4;
        float v[4];
        #pragma unroll
        for (int q = 0; q < 4; q++) {
            float t = Cs[row * C_STRIDE + c4 + q] + __ldg(bias + N0 + c4 + q);
            if (EPI == EPI_BIAS_RES) t += res[roff + q];
            if (EPI == EPI_GELU) {
                t = 0.5f * t * (1.0f + erff(t * 0.70710678118654752f));
                t = f2tf32f(t);            // feeds next GEMM
            }
            v[q] = t;
        }
        *(float4*)(C + roff) = *(float4*)v;
    }
}

// ---------------- windowed attention (output tf32-rounded) ----------------
__global__ __launch_bounds__(256)
void attn_kernel(const float* __restrict__ qkv, float* __restrict__ o)
{
    int blk  = blockIdx.x;
    int head = blk & 3;
    int w    = blk >> 2;
    int bimg = w >> 6;
    int win  = w & 63;
    int wr   = win >> 3, wc = win & 7;

    __shared__ int   tok[TWIN];
    __shared__ float qs[TWIN * 33];
    __shared__ float ks[TWIN * 33];
    __shared__ float vs[TWIN * 33];
    __shared__ float S[TWIN * TWIN];

    int tid = threadIdx.x;
    if (tid < TWIN) {
        int r = tid / WS, c = tid - r * WS;
        tok[tid] = bimg * (RESO * RESO) + (wr * WS + r) * RESO + (wc * WS + c);
    }
    __syncthreads();

    for (int idx = tid; idx < TWIN * HDIM * 3; idx += 256) {
        int which = idx / (TWIN * HDIM);
        int rem   = idx - which * (TWIN * HDIM);
        int t = rem >> 5, d = rem & 31;
        float val = qkv[(size_t)tok[t] * (3 * CDIM) + which * CDIM + head * HDIM + d];
        float* dst = (which == 0) ? qs : (which == 1) ? ks : vs;
        dst[t * 33 + d] = val;
    }
    __syncthreads();

    const float scale = 0.17677669529663687f;
    for (int idx = tid; idx < TWIN * TWIN; idx += 256) {
        int qi = idx / TWIN, ki = idx - qi * TWIN;
        float s = 0.0f;
        #pragma unroll
        for (int d = 0; d < HDIM; d++)
            s = fmaf(qs[qi * 33 + d], ks[ki * 33 + d], s);
        S[idx] = s * scale;
    }
    __syncthreads();

    int warp = tid >> 5, lane = tid & 31;
    for (int row = warp; row < TWIN; row += 8) {
        float v0 = S[row * TWIN + lane];
        float v1 = (lane + 32 < TWIN) ? S[row * TWIN + lane + 32] : -3.4e38f;
        float m = fmaxf(v0, v1);
        #pragma unroll
        for (int off = 16; off; off >>= 1)
            m = fmaxf(m, __shfl_xor_sync(0xffffffffu, m, off));
        float e0 = __expf(v0 - m);
        float e1 = (lane + 32 < TWIN) ? __expf(v1 - m) : 0.0f;
        float s = e0 + e1;
        #pragma unroll
        for (int off = 16; off; off >>= 1)
            s += __shfl_xor_sync(0xffffffffu, s, off);
        float inv = 1.0f / s;
        S[row * TWIN + lane] = e0 * inv;
        if (lane + 32 < TWIN) S[row * TWIN + lane + 32] = e1 * inv;
    }
    __syncthreads();

    for (int idx = tid; idx < TWIN * HDIM; idx += 256) {
        int qi = idx >> 5, d = idx & 31;
        float acc = 0.0f;
        #pragma unroll
        for (int ki = 0; ki < TWIN; ki++)
            acc = fmaf(S[qi * TWIN + ki], vs[ki * 33 + d], acc);
        o[(size_t)tok[qi] * CDIM + head * HDIM + d] = f2tf32f(acc);
    }
}

// ---------------- launch ----------------
extern "C" void kernel_launch(void* const* d_in, const int* in_sizes, int n_in,
                              void* d_out, int out_size)
{
    const float* x      = (const float*)d_in[0];
    const float* ln1_g  = (const float*)d_in[1];
    const float* ln1_b  = (const float*)d_in[2];
    const float* qkv_w  = (const float*)d_in[3];
    const float* qkv_b  = (const float*)d_in[4];
    const float* proj_w = (const float*)d_in[5];
    const float* proj_b = (const float*)d_in[6];
    const float* ln2_g  = (const float*)d_in[7];
    const float* ln2_b  = (const float*)d_in[8];
    const float* mlp_w1 = (const float*)d_in[9];
    const float* mlp_b1 = (const float*)d_in[10];
    const float* mlp_w2 = (const float*)d_in[11];
    const float* mlp_b2 = (const float*)d_in[12];
    float* out = (float*)d_out;

    float *p_ln, *p_qkv, *p_o, *p_x2, *p_h1, *p_wT;
    cudaGetSymbolAddress((void**)&p_ln,  g_ln);
    cudaGetSymbolAddress((void**)&p_qkv, g_qkv);
    cudaGetSymbolAddress((void**)&p_o,   g_o);
    cudaGetSymbolAddress((void**)&p_x2,  g_x2);
    cudaGetSymbolAddress((void**)&p_h1,  g_h1);
    cudaGetSymbolAddress((void**)&p_wT,  g_wT);
    float* wt_qkv  = p_wT;
    float* wt_proj = p_wT + 49152;
    float* wt_w1   = p_wT + 49152 + 16384;
    float* wt_w2   = p_wT + 49152 + 16384 + 65536;

    cudaFuncSetAttribute(tc_gemm<EPI_BIAS>,     cudaFuncAttributeMaxDynamicSharedMemorySize, SMEM_BYTES);
    cudaFuncSetAttribute(tc_gemm<EPI_BIAS_RES>, cudaFuncAttributeMaxDynamicSharedMemorySize, SMEM_BYTES);
    cudaFuncSetAttribute(tc_gemm<EPI_GELU>,     cudaFuncAttributeMaxDynamicSharedMemorySize, SMEM_BYTES);

    dim3 blk(256);
    const int MT = NTOK / 128;  // 784

    // weight rounding (tf32, layout preserved)
    round_tf32<<<(49152 + 255) / 256, blk>>>(qkv_w,  wt_qkv,  49152);
    round_tf32<<<(16384 + 255) / 256, blk>>>(proj_w, wt_proj, 16384);
    round_tf32<<<(65536 + 255) / 256, blk>>>(mlp_w1, wt_w1,   65536);
    round_tf32<<<(65536 + 255) / 256, blk>>>(mlp_w2, wt_w2,   65536);

    // 1. LN1
    ln_kernel<<<(NTOK * 32) / 256, blk>>>(x, ln1_g, ln1_b, p_ln);
    // 2. QKV = ln1 @ qkv_w + qkv_b
    tc_gemm<EPI_BIAS><<<dim3(3, MT), blk, SMEM_BYTES>>>(
        p_ln, wt_qkv, qkv_b, nullptr, p_qkv, 3 * CDIM, CDIM);
    // 3. attention
    attn_kernel<<<NWIN * NHEAD, blk>>>(p_qkv, p_o);
    // 4. x2 = x + proj(o)
    tc_gemm<EPI_BIAS_RES><<<dim3(1, MT), blk, SMEM_BYTES>>>(
        p_o, wt_proj, proj_b, x, p_x2, CDIM, CDIM);
    // 5. LN2
    ln_kernel<<<(NTOK * 32) / 256, blk>>>(p_x2, ln2_g, ln2_b, p_ln);
    // 6. h1 = gelu(mlp1)
    tc_gemm<EPI_GELU><<<dim3(4, MT), blk, SMEM_BYTES>>>(
        p_ln, wt_w1, mlp_b1, nullptr, p_h1, HID, CDIM);
    // 7. out = x2 + mlp2(h1)
    tc_gemm<EPI_BIAS_RES><<<dim3(1, MT), blk, SMEM_BYTES>>>(
        p_h1, wt_w2, mlp_b2, p_x2, out, CDIM, HID);
}

// round 4
// speedup vs baseline: 1.5689x; 1.1739x over previous
#include <cuda_runtime.h>
#include <cuda_bf16.h>
#include <mma.h>
#include <math.h>
#include <stdint.h>

using namespace nvcuda;

// ---------------- problem constants ----------------
#define RESO 56
#define WS   7
#define CDIM 128
#define NHEAD 4
#define HDIM 32
#define HID  512
#define BATCH 32
#define NTOK (BATCH * RESO * RESO)      // 100352
#define NWIN (BATCH * 8 * 8)            // 2048 windows
#define TWIN 49

// ---------------- device scratch ----------------
__device__ float g_ln [(size_t)NTOK * CDIM];
__device__ float g_qkv[(size_t)NTOK * 3 * CDIM];
__device__ float g_o  [(size_t)NTOK * CDIM];
__device__ float g_x2 [(size_t)NTOK * CDIM];
__device__ float g_h1 [(size_t)NTOK * HID];
// tf32-rounded weights, [K,N] layout: qkv(128x384) proj(128x128) w1(128x512) w2(512x128)
__device__ float g_wT [49152 + 16384 + 65536 + 65536];

__device__ __forceinline__ float f2tf32f(float f) {
    uint32_t r; asm("cvt.rna.tf32.f32 %0, %1;" : "=r"(r) : "f"(f));
    return __uint_as_float(r);
}
__device__ __forceinline__ uint32_t smem_u32(const void* p) {
    uint32_t a;
    asm("{ .reg .u64 t; cvta.to.shared.u64 t, %1; cvt.u32.u64 %0, t; }" : "=r"(a) : "l"(p));
    return a;
}
__device__ __forceinline__ void cp_async16(uint32_t saddr, const void* gaddr) {
    asm volatile("cp.async.ca.shared.global [%0], [%1], 16;" :: "r"(saddr), "l"(gaddr));
}
#define CP_COMMIT() asm volatile("cp.async.commit_group;" ::: "memory")
#define CP_WAIT(n)  asm volatile("cp.async.wait_group %0;" :: "n"(n) : "memory")

// ---------------- LayerNorm (tf32-rounded output) ----------------
__global__ void ln_kernel(const float* __restrict__ x, const float* __restrict__ g,
                          const float* __restrict__ b, float* __restrict__ out)
{
    int gwarp = (blockIdx.x * blockDim.x + threadIdx.x) >> 5;
    int lane  = threadIdx.x & 31;
    if (gwarp >= NTOK) return;
    float4 v = ((const float4*)(x + (size_t)gwarp * CDIM))[lane];
    float s  = v.x + v.y + v.z + v.w;
    float ss = v.x*v.x + v.y*v.y + v.z*v.z + v.w*v.w;
    #pragma unroll
    for (int off = 16; off; off >>= 1) {
        s  += __shfl_xor_sync(0xffffffffu, s,  off);
        ss += __shfl_xor_sync(0xffffffffu, ss, off);
    }
    float mean = s * (1.0f / CDIM);
    float var  = ss * (1.0f / CDIM) - mean * mean;
    float rstd = rsqrtf(var + 1e-5f);
    float4 gg = ((const float4*)g)[lane];
    float4 bb = ((const float4*)b)[lane];
    float4 o;
    o.x = f2tf32f((v.x - mean) * rstd * gg.x + bb.x);
    o.y = f2tf32f((v.y - mean) * rstd * gg.y + bb.y);
    o.z = f2tf32f((v.z - mean) * rstd * gg.z + bb.z);
    o.w = f2tf32f((v.w - mean) * rstd * gg.w + bb.w);
    ((float4*)(out + (size_t)gwarp * CDIM))[lane] = o;
}

// ---------------- single-pass weight rounding (all 4 weights) -------------
#define W_QKV_N 49152
#define W_PROJ_N 16384
#define W_W1_N 65536
#define W_W2_N 65536
#define W_TOTAL (W_QKV_N + W_PROJ_N + W_W1_N + W_W2_N)

__global__ void round_all_tf32(const float* __restrict__ w0, const float* __restrict__ w1,
                               const float* __restrict__ w2, const float* __restrict__ w3,
                               float* __restrict__ WT)
{
    int idx = blockIdx.x * 256 + threadIdx.x;
    if (idx >= W_TOTAL) return;
    float v;
    if (idx < W_QKV_N)                      v = w0[idx];
    else if (idx < W_QKV_N + W_PROJ_N)      v = w1[idx - W_QKV_N];
    else if (idx < W_QKV_N + W_PROJ_N + W_W1_N)
                                            v = w2[idx - W_QKV_N - W_PROJ_N];
    else                                    v = w3[idx - W_QKV_N - W_PROJ_N - W_W1_N];
    WT[idx] = f2tf32f(v);
}

// ---------------- WMMA tf32 GEMM: C[M,N] = A[M,K] @ B[K,N] -----------------
// CTA tile 128x128, 8 warps (2x4), warp tile 64x32 (4x2 of m16n16k8).
// K-chunks of 32, double-buffered cp.async. Inputs pre-rounded to tf32.
enum { EPI_BIAS = 0, EPI_BIAS_RES = 1, EPI_GELU = 2, EPI_RES_LN2 = 3 };

#define A_STRIDE 36
#define B_STRIDE 136
#define C_STRIDE 132
#define ABUF (128 * A_STRIDE * 4)          // 18432 B
#define BBUF (32 * B_STRIDE * 4)           // 17408 B
#define SMEM_BYTES (2 * ABUF + 2 * BBUF)   // 71680 B

template <int EPI>
__global__ void __launch_bounds__(256, 2)
tc_gemm(const float* __restrict__ A, const float* __restrict__ B,
        const float* __restrict__ bias, const float* __restrict__ res,
        float* __restrict__ C, int N, int K,
        const float* __restrict__ lng, const float* __restrict__ lnb,
        float* __restrict__ C2)
{
    extern __shared__ char smem[];
    uint32_t sbase = smem_u32(smem);
    const int tid = threadIdx.x;
    const int wid = tid >> 5;
    const int warpM = wid & 1;
    const int warpN = wid >> 1;
    const int M0 = blockIdx.y * 128;
    const int N0 = blockIdx.x * 128;

    const float* Abase = A + (size_t)M0 * K;
    const float* Bbase = B + N0;
    const int nchunk = K >> 5;

    wmma::fragment<wmma::accumulator, 16, 16, 8, float> acc[4][2];
    #pragma unroll
    for (int i = 0; i < 4; i++)
        #pragma unroll
        for (int j = 0; j < 2; j++) wmma::fill_fragment(acc[i][j], 0.0f);

    auto load_chunk = [&](int c) {
        int buf = c & 1;
        uint32_t sa = sbase + buf * ABUF;
        uint32_t sb = sbase + 2 * ABUF + buf * BBUF;
        int k0 = c << 5;
        #pragma unroll
        for (int q = 0; q < 4; q++) {
            int e = tid * 4 + q;
            int row = e >> 3, c16 = e & 7;
            cp_async16(sa + row * (A_STRIDE * 4) + c16 * 16,
                       Abase + (size_t)row * K + k0 + c16 * 4);
        }
        #pragma unroll
        for (int q = 0; q < 4; q++) {
            int e = tid * 4 + q;
            int row = e >> 5, c16 = e & 31;
            cp_async16(sb + row * (B_STRIDE * 4) + c16 * 16,
                       Bbase + (size_t)(k0 + row) * N + c16 * 4);
        }
    };

    load_chunk(0);
    CP_COMMIT();

    for (int c = 0; c < nchunk; c++) {
        if (c + 1 < nchunk) {
            load_chunk(c + 1);
            CP_COMMIT();
            CP_WAIT(1);
        } else {
            CP_WAIT(0);
        }
        __syncthreads();

        int buf = c & 1;
        const float* As = (const float*)(smem + buf * ABUF);
        const float* Bs = (const float*)(smem + 2 * ABUF + buf * BBUF);
        #pragma unroll
        for (int ks = 0; ks < 4; ks++) {
            wmma::fragment<wmma::matrix_a, 16, 16, 8, wmma::precision::tf32, wmma::row_major> af[4];
            wmma::fragment<wmma::matrix_b, 16, 16, 8, wmma::precision::tf32, wmma::row_major> bf[2];
            #pragma unroll
            for (int i = 0; i < 4; i++)
                wmma::load_matrix_sync(af[i],
                    As + (warpM * 64 + i * 16) * A_STRIDE + ks * 8, A_STRIDE);
            #pragma unroll
            for (int j = 0; j < 2; j++)
                wmma::load_matrix_sync(bf[j],
                    Bs + (ks * 8) * B_STRIDE + warpN * 32 + j * 16, B_STRIDE);
            #pragma unroll
            for (int i = 0; i < 4; i++)
                #pragma unroll
                for (int j = 0; j < 2; j++)
                    wmma::mma_sync(acc[i][j], af[i], bf[j], acc[i][j]);
        }
        __syncthreads();
    }

    // stage accumulators in smem
    float* Cs = (float*)smem;
    #pragma unroll
    for (int i = 0; i < 4; i++)
        #pragma unroll
        for (int j = 0; j < 2; j++)
            wmma::store_matrix_sync(
                Cs + (warpM * 64 + i * 16) * C_STRIDE + warpN * 32 + j * 16,
                acc[i][j], C_STRIDE, wmma::mem_row_major);
    __syncthreads();

    // epilogue: one warp owns one full output row per iteration (32 lanes x 4)
    #pragma unroll
    for (int e0 = 0; e0 < 16; e0++) {
        int e = tid + e0 * 256;
        int row = e >> 5;
        int c4  = (e & 31) * 4;
        size_t roff = (size_t)(M0 + row) * N + N0 + c4;
        float v[4];
        #pragma unroll
        for (int q = 0; q < 4; q++) {
            float t = Cs[row * C_STRIDE + c4 + q] + __ldg(bias + N0 + c4 + q);
            if (EPI == EPI_BIAS_RES || EPI == EPI_RES_LN2) t += res[roff + q];
            if (EPI == EPI_GELU) {
                t = 0.5f * t * (1.0f + erff(t * 0.70710678118654752f));
                t = f2tf32f(t);
            }
            v[q] = t;
        }
        if (EPI == EPI_RES_LN2) {
            // N==128 here: this warp's 128 values are the whole token row.
            float s  = v[0] + v[1] + v[2] + v[3];
            float ss = v[0]*v[0] + v[1]*v[1] + v[2]*v[2] + v[3]*v[3];
            #pragma unroll
            for (int off = 16; off; off >>= 1) {
                s  += __shfl_xor_sync(0xffffffffu, s,  off);
                ss += __shfl_xor_sync(0xffffffffu, ss, off);
            }
            float mean = s * (1.0f / CDIM);
            float var  = ss * (1.0f / CDIM) - mean * mean;
            float rstd = rsqrtf(var + 1e-5f);
            float lnv[4];
            #pragma unroll
            for (int q = 0; q < 4; q++)
                lnv[q] = f2tf32f((v[q] - mean) * rstd * __ldg(lng + c4 + q)
                                 + __ldg(lnb + c4 + q));
            *(float4*)(C2 + roff) = *(float4*)lnv;
        }
        *(float4*)(C + roff) = *(float4*)v;
    }
}

// ---------------- windowed attention (register-blocked) ----------------
// block = (window, head). S tiles 4x2 per thread with float2 smem loads.
#define QS_STRIDE 34
#define S_STRIDE  50

__global__ __launch_bounds__(256)
void attn_kernel(const float* __restrict__ qkv, float* __restrict__ o)
{
    int blk  = blockIdx.x;
    int head = blk & 3;
    int w    = blk >> 2;
    int bimg = w >> 6;
    int win  = w & 63;
    int wr   = win >> 3, wc = win & 7;

    __shared__ int tok[TWIN];
    __shared__ __align__(16) float qs[52 * QS_STRIDE];
    __shared__ __align__(16) float ks[50 * QS_STRIDE];
    __shared__ __align__(16) float vs[49 * QS_STRIDE];
    __shared__ __align__(16) float S[52 * S_STRIDE];

    int tid = threadIdx.x;
    if (tid < TWIN) {
        int r = tid / WS, c = tid - r * WS;
        tok[tid] = bimg * (RESO * RESO) + (wr * WS + r) * RESO + (wc * WS + c);
    }
    // zero padding rows: qs rows 49..51, ks row 49
    if (tid < 3 * QS_STRIDE) qs[49 * QS_STRIDE + tid] = 0.0f;
    if (tid >= 128 && tid < 128 + QS_STRIDE) ks[49 * QS_STRIDE + (tid - 128)] = 0.0f;
    __syncthreads();

    for (int idx = tid; idx < TWIN * HDIM * 3; idx += 256) {
        int which = idx / (TWIN * HDIM);
        int rem   = idx - which * (TWIN * HDIM);
        int t = rem >> 5, d = rem & 31;
        float val = qkv[(size_t)tok[t] * (3 * CDIM) + which * CDIM + head * HDIM + d];
        float* dst = (which == 0) ? qs : (which == 1) ? ks : vs;
        dst[t * QS_STRIDE + d] = val;
    }
    __syncthreads();

    // S = q @ k^T * scale : 13 qi-groups(4) x 25 ki-groups(2) = 325 tiles
    const float scale = 0.17677669529663687f;
    for (int t = tid; t < 13 * 25; t += 256) {
        int qg = t / 25, kg = t - qg * 25;
        int qi0 = qg * 4, ki0 = kg * 2;
        float a00 = 0, a01 = 0, a10 = 0, a11 = 0,
              a20 = 0, a21 = 0, a30 = 0, a31 = 0;
        #pragma unroll
        for (int dp = 0; dp < 16; dp++) {
            float2 k0 = *(const float2*)&ks[ki0 * QS_STRIDE + 2 * dp];
            float2 k1 = *(const float2*)&ks[(ki0 + 1) * QS_STRIDE + 2 * dp];
            float2 q0 = *(const float2*)&qs[(qi0 + 0) * QS_STRIDE + 2 * dp];
            float2 q1 = *(const float2*)&qs[(qi0 + 1) * QS_STRIDE + 2 * dp];
            float2 q2 = *(const float2*)&qs[(qi0 + 2) * QS_STRIDE + 2 * dp];
            float2 q3 = *(const float2*)&qs[(qi0 + 3) * QS_STRIDE + 2 * dp];
            a00 = fmaf(q0.x, k0.x, fmaf(q0.y, k0.y, a00));
            a01 = fmaf(q0.x, k1.x, fmaf(q0.y, k1.y, a01));
            a10 = fmaf(q1.x, k0.x, fmaf(q1.y, k0.y, a10));
            a11 = fmaf(q1.x, k1.x, fmaf(q1.y, k1.y, a11));
            a20 = fmaf(q2.x, k0.x, fmaf(q2.y, k0.y, a20));
            a21 = fmaf(q2.x, k1.x, fmaf(q2.y, k1.y, a21));
            a30 = fmaf(q3.x, k0.x, fmaf(q3.y, k0.y, a30));
            a31 = fmaf(q3.x, k1.x, fmaf(q3.y, k1.y, a31));
        }
        float av[4][2] = {{a00,a01},{a10,a11},{a20,a21},{a30,a31}};
        #pragma unroll
        for (int i = 0; i < 4; i++)
            if (qi0 + i < TWIN)
                #pragma unroll
                for (int j = 0; j < 2; j++)
                    if (ki0 + j < TWIN)
                        S[(qi0 + i) * S_STRIDE + ki0 + j] = av[i][j] * scale;
    }
    __syncthreads();

    // softmax per row
    int warp = tid >> 5, lane = tid & 31;
    for (int row = warp; row < TWIN; row += 8) {
        float v0 = S[row * S_STRIDE + lane];
        float v1 = (lane + 32 < TWIN) ? S[row * S_STRIDE + lane + 32] : -3.4e38f;
        float m = fmaxf(v0, v1);
        #pragma unroll
        for (int off = 16; off; off >>= 1)
            m = fmaxf(m, __shfl_xor_sync(0xffffffffu, m, off));
        float e0 = __expf(v0 - m);
        float e1 = (lane + 32 < TWIN) ? __expf(v1 - m) : 0.0f;
        float s = e0 + e1;
        #pragma unroll
        for (int off = 16; off; off >>= 1)
            s += __shfl_xor_sync(0xffffffffu, s, off);
        float inv = 1.0f / s;
        S[row * S_STRIDE + lane] = e0 * inv;
        if (lane + 32 < TWIN) S[row * S_STRIDE + lane + 32] = e1 * inv;
    }
    __syncthreads();

    // O = P @ V : 13 qi-groups(4) x 16 d-pairs = 208 tiles
    for (int t = tid; t < 13 * 16; t += 256) {
        int qg = t / 16, dp = t - qg * 16;
        int qi0 = qg * 4, d = dp * 2;
        float ax0 = 0, ay0 = 0, ax1 = 0, ay1 = 0,
              ax2 = 0, ay2 = 0, ax3 = 0, ay3 = 0;
        for (int ki = 0; ki < TWIN; ki++) {
            float2 vv = *(const float2*)&vs[ki * QS_STRIDE + d];
            float s0 = S[(qi0 + 0) * S_STRIDE + ki];
            float s1 = S[(qi0 + 1) * S_STRIDE + ki];
            float s2 = S[(qi0 + 2) * S_STRIDE + ki];
            float s3 = S[(qi0 + 3) * S_STRIDE + ki];
            ax0 = fmaf(s0, vv.x, ax0); ay0 = fmaf(s0, vv.y, ay0);
            ax1 = fmaf(s1, vv.x, ax1); ay1 = fmaf(s1, vv.y, ay1);
            ax2 = fmaf(s2, vv.x, ax2); ay2 = fmaf(s2, vv.y, ay2);
            ax3 = fmaf(s3, vv.x, ax3); ay3 = fmaf(s3, vv.y, ay3);
        }
        float axs[4] = {ax0, ax1, ax2, ax3};
        float ays[4] = {ay0, ay1, ay2, ay3};
        #pragma unroll
        for (int i = 0; i < 4; i++) {
            if (qi0 + i < TWIN) {
                float* dst = o + (size_t)tok[qi0 + i] * CDIM + head * HDIM + d;
                dst[0] = f2tf32f(axs[i]);
                dst[1] = f2tf32f(ays[i]);
            }
        }
    }
}

// ---------------- launch ----------------
extern "C" void kernel_launch(void* const* d_in, const int* in_sizes, int n_in,
                              void* d_out, int out_size)
{
    const float* x      = (const float*)d_in[0];
    const float* ln1_g  = (const float*)d_in[1];
    const float* ln1_b  = (const float*)d_in[2];
    const float* qkv_w  = (const float*)d_in[3];
    const float* qkv_b  = (const float*)d_in[4];
    const float* proj_w = (const float*)d_in[5];
    const float* proj_b = (const float*)d_in[6];
    const float* ln2_g  = (const float*)d_in[7];
    const float* ln2_b  = (const float*)d_in[8];
    const float* mlp_w1 = (const float*)d_in[9];
    const float* mlp_b1 = (const float*)d_in[10];
    const float* mlp_w2 = (const float*)d_in[11];
    const float* mlp_b2 = (const float*)d_in[12];
    float* out = (float*)d_out;

    float *p_ln, *p_qkv, *p_o, *p_x2, *p_h1, *p_wT;
    cudaGetSymbolAddress((void**)&p_ln,  g_ln);
    cudaGetSymbolAddress((void**)&p_qkv, g_qkv);
    cudaGetSymbolAddress((void**)&p_o,   g_o);
    cudaGetSymbolAddress((void**)&p_x2,  g_x2);
    cudaGetSymbolAddress((void**)&p_h1,  g_h1);
    cudaGetSymbolAddress((void**)&p_wT,  g_wT);
    float* wt_qkv  = p_wT;
    float* wt_proj = p_wT + W_QKV_N;
    float* wt_w1   = p_wT + W_QKV_N + W_PROJ_N;
    float* wt_w2   = p_wT + W_QKV_N + W_PROJ_N + W_W1_N;

    cudaFuncSetAttribute(tc_gemm<EPI_BIAS>,     cudaFuncAttributeMaxDynamicSharedMemorySize, SMEM_BYTES);
    cudaFuncSetAttribute(tc_gemm<EPI_BIAS_RES>, cudaFuncAttributeMaxDynamicSharedMemorySize, SMEM_BYTES);
    cudaFuncSetAttribute(tc_gemm<EPI_GELU>,     cudaFuncAttributeMaxDynamicSharedMemorySize, SMEM_BYTES);
    cudaFuncSetAttribute(tc_gemm<EPI_RES_LN2>,  cudaFuncAttributeMaxDynamicSharedMemorySize, SMEM_BYTES);

    dim3 blk(256);
    const int MT = NTOK / 128;  // 784

    // 0. weight rounding (single launch)
    round_all_tf32<<<(W_TOTAL + 255) / 256, blk>>>(qkv_w, proj_w, mlp_w1, mlp_w2, p_wT);
    // 1. LN1
    ln_kernel<<<(NTOK * 32) / 256, blk>>>(x, ln1_g, ln1_b, p_ln);
    // 2. QKV = ln1 @ qkv_w + qkv_b
    tc_gemm<EPI_BIAS><<<dim3(3, MT), blk, SMEM_BYTES>>>(
        p_ln, wt_qkv, qkv_b, nullptr, p_qkv, 3 * CDIM, CDIM, nullptr, nullptr, nullptr);
    // 3. attention
    attn_kernel<<<NWIN * NHEAD, blk>>>(p_qkv, p_o);
    // 4. x2 = x + proj(o); fused LN2 -> p_ln (tf32)
    tc_gemm<EPI_RES_LN2><<<dim3(1, MT), blk, SMEM_BYTES>>>(
        p_o, wt_proj, proj_b, x, p_x2, CDIM, CDIM, ln2_g, ln2_b, p_ln);
    // 5. h1 = gelu(ln2 @ w1 + b1)
    tc_gemm<EPI_GELU><<<dim3(4, MT), blk, SMEM_BYTES>>>(
        p_ln, wt_w1, mlp_b1, nullptr, p_h1, HID, CDIM, nullptr, nullptr, nullptr);
    // 6. out = x2 + h1 @ w2 + b2
    tc_gemm<EPI_BIAS_RES><<<dim3(1, MT), blk, SMEM_BYTES>>>(
        p_h1, wt_w2, mlp_b2, p_x2, out, CDIM, HID, nullptr, nullptr, nullptr);
}

// round 5
// speedup vs baseline: 1.6156x; 1.0298x over previous
#include <cuda_runtime.h>
#include <cuda_bf16.h>
#include <mma.h>
#include <math.h>
#include <stdint.h>

using namespace nvcuda;

// ---------------- problem constants ----------------
#define RESO 56
#define WS   7
#define CDIM 128
#define NHEAD 4
#define HDIM 32
#define HID  512
#define BATCH 32
#define NTOK (BATCH * RESO * RESO)      // 100352
#define NWIN (BATCH * 8 * 8)            // 2048 windows
#define TWIN 49

// ---------------- device scratch ----------------
__device__ float g_ln [(size_t)NTOK * CDIM];
__device__ float g_qkv[(size_t)NTOK * 3 * CDIM];
__device__ float g_o  [(size_t)NTOK * CDIM];
__device__ float g_x2 [(size_t)NTOK * CDIM];
__device__ float g_h1 [(size_t)NTOK * HID];
__device__ float g_wT [49152 + 16384 + 65536 + 65536];

__device__ __forceinline__ float f2tf32f(float f) {
    uint32_t r; asm("cvt.rna.tf32.f32 %0, %1;" : "=r"(r) : "f"(f));
    return __uint_as_float(r);
}
__device__ __forceinline__ uint32_t smem_u32(const void* p) {
    uint32_t a;
    asm("{ .reg .u64 t; cvta.to.shared.u64 t, %1; cvt.u32.u64 %0, t; }" : "=r"(a) : "l"(p));
    return a;
}
__device__ __forceinline__ void cp_async16(uint32_t saddr, const void* gaddr) {
    asm volatile("cp.async.ca.shared.global [%0], [%1], 16;" :: "r"(saddr), "l"(gaddr));
}
#define CP_COMMIT() asm volatile("cp.async.commit_group;" ::: "memory")
#define CP_WAIT(n)  asm volatile("cp.async.wait_group %0;" :: "n"(n) : "memory")

// ---------------- LayerNorm (tf32-rounded output) ----------------
__global__ void ln_kernel(const float* __restrict__ x, const float* __restrict__ g,
                          const float* __restrict__ b, float* __restrict__ out)
{
    int gwarp = (blockIdx.x * blockDim.x + threadIdx.x) >> 5;
    int lane  = threadIdx.x & 31;
    if (gwarp >= NTOK) return;
    float4 v = ((const float4*)(x + (size_t)gwarp * CDIM))[lane];
    float s  = v.x + v.y + v.z + v.w;
    float ss = v.x*v.x + v.y*v.y + v.z*v.z + v.w*v.w;
    #pragma unroll
    for (int off = 16; off; off >>= 1) {
        s  += __shfl_xor_sync(0xffffffffu, s,  off);
        ss += __shfl_xor_sync(0xffffffffu, ss, off);
    }
    float mean = s * (1.0f / CDIM);
    float var  = ss * (1.0f / CDIM) - mean * mean;
    float rstd = rsqrtf(var + 1e-5f);
    float4 gg = ((const float4*)g)[lane];
    float4 bb = ((const float4*)b)[lane];
    float4 o;
    o.x = f2tf32f((v.x - mean) * rstd * gg.x + bb.x);
    o.y = f2tf32f((v.y - mean) * rstd * gg.y + bb.y);
    o.z = f2tf32f((v.z - mean) * rstd * gg.z + bb.z);
    o.w = f2tf32f((v.w - mean) * rstd * gg.w + bb.w);
    ((float4*)(out + (size_t)gwarp * CDIM))[lane] = o;
}

// ---------------- single-pass weight rounding ----------------
#define W_QKV_N 49152
#define W_PROJ_N 16384
#define W_W1_N 65536
#define W_W2_N 65536
#define W_TOTAL (W_QKV_N + W_PROJ_N + W_W1_N + W_W2_N)

__global__ void round_all_tf32(const float* __restrict__ w0, const float* __restrict__ w1,
                               const float* __restrict__ w2, const float* __restrict__ w3,
                               float* __restrict__ WT)
{
    int idx = blockIdx.x * 256 + threadIdx.x;
    if (idx >= W_TOTAL) return;
    float v;
    if (idx < W_QKV_N)                      v = w0[idx];
    else if (idx < W_QKV_N + W_PROJ_N)      v = w1[idx - W_QKV_N];
    else if (idx < W_QKV_N + W_PROJ_N + W_W1_N)
                                            v = w2[idx - W_QKV_N - W_PROJ_N];
    else                                    v = w3[idx - W_QKV_N - W_PROJ_N - W_W1_N];
    WT[idx] = f2tf32f(v);
}

// ---------------- WMMA tf32 GEMM: C[M,N] = A[M,K] @ B[K,N] -----------------
// CTA tile 128x128, 4 warps (2x2), warp tile 64x64 (4x4 of m16n16k8).
// K-chunks of 32, double-buffered cp.async.
enum { EPI_BIAS = 0, EPI_BIAS_RES = 1, EPI_GELU = 2, EPI_RES_LN2 = 3 };

#define A_STRIDE 36
#define B_STRIDE 136
#define C_STRIDE 132
#define ABUF (128 * A_STRIDE * 4)          // 18432 B
#define BBUF (32 * B_STRIDE * 4)           // 17408 B
#define SMEM_BYTES (2 * ABUF + 2 * BBUF)   // 71680 B

template <int EPI>
__global__ void __launch_bounds__(128, 2)
tc_gemm(const float* __restrict__ A, const float* __restrict__ B,
        const float* __restrict__ bias, const float* __restrict__ res,
        float* __restrict__ C, int N, int K,
        const float* __restrict__ lng, const float* __restrict__ lnb,
        float* __restrict__ C2)
{
    extern __shared__ char smem[];
    uint32_t sbase = smem_u32(smem);
    const int tid = threadIdx.x;
    const int wid = tid >> 5;
    const int warpM = wid & 1;          // 0..1 -> 64 rows each
    const int warpN = wid >> 1;         // 0..1 -> 64 cols each
    const int M0 = blockIdx.y * 128;
    const int N0 = blockIdx.x * 128;

    const float* Abase = A + (size_t)M0 * K;
    const float* Bbase = B + N0;
    const int nchunk = K >> 5;

    wmma::fragment<wmma::accumulator, 16, 16, 8, float> acc[4][4];
    #pragma unroll
    for (int i = 0; i < 4; i++)
        #pragma unroll
        for (int j = 0; j < 4; j++) wmma::fill_fragment(acc[i][j], 0.0f);

    auto load_chunk = [&](int c) {
        int buf = c & 1;
        uint32_t sa = sbase + buf * ABUF;
        uint32_t sb = sbase + 2 * ABUF + buf * BBUF;
        int k0 = c << 5;
        #pragma unroll
        for (int q = 0; q < 8; q++) {
            int e = tid + q * 128;          // 1024 chunks of A
            int row = e >> 3, c16 = e & 7;
            cp_async16(sa + row * (A_STRIDE * 4) + c16 * 16,
                       Abase + (size_t)row * K + k0 + c16 * 4);
        }
        #pragma unroll
        for (int q = 0; q < 8; q++) {
            int e = tid + q * 128;          // 1024 chunks of B
            int row = e >> 5, c16 = e & 31;
            cp_async16(sb + row * (B_STRIDE * 4) + c16 * 16,
                       Bbase + (size_t)(k0 + row) * N + c16 * 4);
        }
    };

    load_chunk(0);
    CP_COMMIT();

    for (int c = 0; c < nchunk; c++) {
        if (c + 1 < nchunk) {
            load_chunk(c + 1);
            CP_COMMIT();
            CP_WAIT(1);
        } else {
            CP_WAIT(0);
        }
        __syncthreads();

        int buf = c & 1;
        const float* As = (const float*)(smem + buf * ABUF);
        const float* Bs = (const float*)(smem + 2 * ABUF + buf * BBUF);
        #pragma unroll
        for (int ks = 0; ks < 4; ks++) {
            wmma::fragment<wmma::matrix_a, 16, 16, 8, wmma::precision::tf32, wmma::row_major> af[4];
            wmma::fragment<wmma::matrix_b, 16, 16, 8, wmma::precision::tf32, wmma::row_major> bf[4];
            #pragma unroll
            for (int i = 0; i < 4; i++)
                wmma::load_matrix_sync(af[i],
                    As + (warpM * 64 + i * 16) * A_STRIDE + ks * 8, A_STRIDE);
            #pragma unroll
            for (int j = 0; j < 4; j++)
                wmma::load_matrix_sync(bf[j],
                    Bs + (ks * 8) * B_STRIDE + warpN * 64 + j * 16, B_STRIDE);
            #pragma unroll
            for (int i = 0; i < 4; i++)
                #pragma unroll
                for (int j = 0; j < 4; j++)
                    wmma::mma_sync(acc[i][j], af[i], bf[j], acc[i][j]);
        }
        __syncthreads();
    }

    // stage accumulators in smem
    float* Cs = (float*)smem;
    #pragma unroll
    for (int i = 0; i < 4; i++)
        #pragma unroll
        for (int j = 0; j < 4; j++)
            wmma::store_matrix_sync(
                Cs + (warpM * 64 + i * 16) * C_STRIDE + warpN * 64 + j * 16,
                acc[i][j], C_STRIDE, wmma::mem_row_major);
    __syncthreads();

    // epilogue: each warp owns one full 128-wide row per sub-iteration
    #pragma unroll
    for (int e0 = 0; e0 < 32; e0++) {
        int e = tid + e0 * 128;
        int row = e >> 5;
        int c4  = (e & 31) * 4;
        size_t roff = (size_t)(M0 + row) * N + N0 + c4;
        float v[4];
        #pragma unroll
        for (int q = 0; q < 4; q++) {
            float t = Cs[row * C_STRIDE + c4 + q] + __ldg(bias + N0 + c4 + q);
            if (EPI == EPI_BIAS_RES || EPI == EPI_RES_LN2) t += res[roff + q];
            if (EPI == EPI_GELU) {
                t = 0.5f * t * (1.0f + erff(t * 0.70710678118654752f));
                t = f2tf32f(t);
            }
            v[q] = t;
        }
        if (EPI == EPI_RES_LN2) {
            float s  = v[0] + v[1] + v[2] + v[3];
            float ss = v[0]*v[0] + v[1]*v[1] + v[2]*v[2] + v[3]*v[3];
            #pragma unroll
            for (int off = 16; off; off >>= 1) {
                s  += __shfl_xor_sync(0xffffffffu, s,  off);
                ss += __shfl_xor_sync(0xffffffffu, ss, off);
            }
            float mean = s * (1.0f / CDIM);
            float var  = ss * (1.0f / CDIM) - mean * mean;
            float rstd = rsqrtf(var + 1e-5f);
            float lnv[4];
            #pragma unroll
            for (int q = 0; q < 4; q++)
                lnv[q] = f2tf32f((v[q] - mean) * rstd * __ldg(lng + c4 + q)
                                 + __ldg(lnb + c4 + q));
            *(float4*)(C2 + roff) = *(float4*)lnv;
        }
        *(float4*)(C + roff) = *(float4*)v;
    }
}

// ---------------- windowed attention: transposed-S, 4x4 reg tiles ----------
#define QS_STRIDE 34
#define ST_STRIDE 52

__global__ __launch_bounds__(256)
void attn_kernel(const float* __restrict__ qkv, float* __restrict__ o)
{
    int blk  = blockIdx.x;
    int head = blk & 3;
    int w    = blk >> 2;
    int bimg = w >> 6;
    int win  = w & 63;
    int wr   = win >> 3, wc = win & 7;

    __shared__ int tok[TWIN];
    __shared__ __align__(16) float qs[52 * QS_STRIDE];
    __shared__ __align__(16) float ks[52 * QS_STRIDE];
    __shared__ __align__(16) float vs[49 * QS_STRIDE];
    __shared__ __align__(16) float St[52 * ST_STRIDE];   // St[ki][qi]

    int tid = threadIdx.x;
    if (tid < TWIN) {
        int r = tid / WS, c = tid - r * WS;
        tok[tid] = bimg * (RESO * RESO) + (wr * WS + r) * RESO + (wc * WS + c);
    }
    // zero padding rows 49..51 of qs and ks
    if (tid < 3 * QS_STRIDE) qs[49 * QS_STRIDE + tid] = 0.0f;
    if (tid >= 128 && tid < 128 + 3 * QS_STRIDE) ks[49 * QS_STRIDE + (tid - 128)] = 0.0f;
    __syncthreads();

    for (int idx = tid; idx < TWIN * HDIM * 3; idx += 256) {
        int which = idx / (TWIN * HDIM);
        int rem   = idx - which * (TWIN * HDIM);
        int t = rem >> 5, d = rem & 31;
        float val = qkv[(size_t)tok[t] * (3 * CDIM) + which * CDIM + head * HDIM + d];
        float* dst = (which == 0) ? qs : (which == 1) ? ks : vs;
        dst[t * QS_STRIDE + d] = val;
    }
    __syncthreads();

    // S^T = (q @ k^T)^T * scale : 13x13 = 169 tiles of 4x4, single pass
    const float scale = 0.17677669529663687f;
    if (tid < 169) {
        int qg = tid / 13, kg = tid - qg * 13;
        int qi0 = qg * 4, ki0 = kg * 4;
        float a[4][4];
        #pragma unroll
        for (int i = 0; i < 4; i++)
            #pragma unroll
            for (int j = 0; j < 4; j++) a[i][j] = 0.0f;
        #pragma unroll
        for (int dp = 0; dp < 16; dp++) {
            float2 kk[4], qq[4];
            #pragma unroll
            for (int j = 0; j < 4; j++)
                kk[j] = *(const float2*)&ks[(ki0 + j) * QS_STRIDE + 2 * dp];
            #pragma unroll
            for (int i = 0; i < 4; i++)
                qq[i] = *(const float2*)&qs[(qi0 + i) * QS_STRIDE + 2 * dp];
            #pragma unroll
            for (int i = 0; i < 4; i++)
                #pragma unroll
                for (int j = 0; j < 4; j++)
                    a[i][j] = fmaf(qq[i].x, kk[j].x, fmaf(qq[i].y, kk[j].y, a[i][j]));
        }
        #pragma unroll
        for (int j = 0; j < 4; j++) {
            float4 vv = make_float4(a[0][j] * scale, a[1][j] * scale,
                                    a[2][j] * scale, a[3][j] * scale);
            *(float4*)&St[(ki0 + j) * ST_STRIDE + qi0] = vv;  // transposed store
        }
    }
    __syncthreads();

    // softmax over ki for each qi (column of St)
    int warp = tid >> 5, lane = tid & 31;
    for (int qi = warp; qi < TWIN; qi += 8) {
        float v0 = St[lane * ST_STRIDE + qi];
        float v1 = (lane + 32 < TWIN) ? St[(lane + 32) * ST_STRIDE + qi] : -3.4e38f;
        float m = fmaxf(v0, v1);
        #pragma unroll
        for (int off = 16; off; off >>= 1)
            m = fmaxf(m, __shfl_xor_sync(0xffffffffu, m, off));
        float e0 = __expf(v0 - m);
        float e1 = (lane + 32 < TWIN) ? __expf(v1 - m) : 0.0f;
        float s = e0 + e1;
        #pragma unroll
        for (int off = 16; off; off >>= 1)
            s += __shfl_xor_sync(0xffffffffu, s, off);
        float inv = 1.0f / s;
        St[lane * ST_STRIDE + qi] = e0 * inv;
        if (lane + 32 < TWIN) St[(lane + 32) * ST_STRIDE + qi] = e1 * inv;
    }
    __syncthreads();

    // O = P @ V : 13 qi-groups(4) x 16 d-pairs = 208 tiles, single pass
    if (tid < 208) {
        int qg = tid / 16, dp = tid - qg * 16;
        int qi0 = qg * 4, d = dp * 2;
        float ax[4] = {0, 0, 0, 0}, ay[4] = {0, 0, 0, 0};
        for (int ki = 0; ki < TWIN; ki++) {
            float4 sv = *(const float4*)&St[ki * ST_STRIDE + qi0];
            float2 vv = *(const float2*)&vs[ki * QS_STRIDE + d];
            ax[0] = fmaf(sv.x, vv.x, ax[0]); ay[0] = fmaf(sv.x, vv.y, ay[0]);
            ax[1] = fmaf(sv.y, vv.x, ax[1]); ay[1] = fmaf(sv.y, vv.y, ay[1]);
            ax[2] = fmaf(sv.z, vv.x, ax[2]); ay[2] = fmaf(sv.z, vv.y, ay[2]);
            ax[3] = fmaf(sv.w, vv.x, ax[3]); ay[3] = fmaf(sv.w, vv.y, ay[3]);
        }
        #pragma unroll
        for (int i = 0; i < 4; i++) {
            if (qi0 + i < TWIN) {
                float* dst = o + (size_t)tok[qi0 + i] * CDIM + head * HDIM + d;
                dst[0] = f2tf32f(ax[i]);
                dst[1] = f2tf32f(ay[i]);
            }
        }
    }
}

// ---------------- launch ----------------
extern "C" void kernel_launch(void* const* d_in, const int* in_sizes, int n_in,
                              void* d_out, int out_size)
{
    const float* x      = (const float*)d_in[0];
    const float* ln1_g  = (const float*)d_in[1];
    const float* ln1_b  = (const float*)d_in[2];
    const float* qkv_w  = (const float*)d_in[3];
    const float* qkv_b  = (const float*)d_in[4];
    const float* proj_w = (const float*)d_in[5];
    const float* proj_b = (const float*)d_in[6];
    const float* ln2_g  = (const float*)d_in[7];
    const float* ln2_b  = (const float*)d_in[8];
    const float* mlp_w1 = (const float*)d_in[9];
    const float* mlp_b1 = (const float*)d_in[10];
    const float* mlp_w2 = (const float*)d_in[11];
    const float* mlp_b2 = (const float*)d_in[12];
    float* out = (float*)d_out;

    float *p_ln, *p_qkv, *p_o, *p_x2, *p_h1, *p_wT;
    cudaGetSymbolAddress((void**)&p_ln,  g_ln);
    cudaGetSymbolAddress((void**)&p_qkv, g_qkv);
    cudaGetSymbolAddress((void**)&p_o,   g_o);
    cudaGetSymbolAddress((void**)&p_x2,  g_x2);
    cudaGetSymbolAddress((void**)&p_h1,  g_h1);
    cudaGetSymbolAddress((void**)&p_wT,  g_wT);
    float* wt_qkv  = p_wT;
    float* wt_proj = p_wT + W_QKV_N;
    float* wt_w1   = p_wT + W_QKV_N + W_PROJ_N;
    float* wt_w2   = p_wT + W_QKV_N + W_PROJ_N + W_W1_N;

    cudaFuncSetAttribute(tc_gemm<EPI_BIAS>,     cudaFuncAttributeMaxDynamicSharedMemorySize, SMEM_BYTES);
    cudaFuncSetAttribute(tc_gemm<EPI_BIAS_RES>, cudaFuncAttributeMaxDynamicSharedMemorySize, SMEM_BYTES);
    cudaFuncSetAttribute(tc_gemm<EPI_GELU>,     cudaFuncAttributeMaxDynamicSharedMemorySize, SMEM_BYTES);
    cudaFuncSetAttribute(tc_gemm<EPI_RES_LN2>,  cudaFuncAttributeMaxDynamicSharedMemorySize, SMEM_BYTES);

    const int MT = NTOK / 128;  // 784

    // 0. weight rounding
    round_all_tf32<<<(W_TOTAL + 255) / 256, 256>>>(qkv_w, proj_w, mlp_w1, mlp_w2, p_wT);
    // 1. LN1
    ln_kernel<<<(NTOK * 32) / 256, 256>>>(x, ln1_g, ln1_b, p_ln);
    // 2. QKV = ln1 @ qkv_w + qkv_b
    tc_gemm<EPI_BIAS><<<dim3(3, MT), 128, SMEM_BYTES>>>(
        p_ln, wt_qkv, qkv_b, nullptr, p_qkv, 3 * CDIM, CDIM, nullptr, nullptr, nullptr);
    // 3. attention
    attn_kernel<<<NWIN * NHEAD, 256>>>(p_qkv, p_o);
    // 4. x2 = x + proj(o); fused LN2 -> p_ln
    tc_gemm<EPI_RES_LN2><<<dim3(1, MT), 128, SMEM_BYTES>>>(
        p_o, wt_proj, proj_b, x, p_x2, CDIM, CDIM, ln2_g, ln2_b, p_ln);
    // 5. h1 = gelu(ln2 @ w1 + b1)
    tc_gemm<EPI_GELU><<<dim3(4, MT), 128, SMEM_BYTES>>>(
        p_ln, wt_w1, mlp_b1, nullptr, p_h1, HID, CDIM, nullptr, nullptr, nullptr);
    // 6. out = x2 + h1 @ w2 + b2
    tc_gemm<EPI_BIAS_RES><<<dim3(1, MT), 128, SMEM_BYTES>>>(
        p_h1, wt_w2, mlp_b2, p_x2, out, CDIM, HID, nullptr, nullptr, nullptr);
}

// round 6
// speedup vs baseline: 1.6331x; 1.0108x over previous
#include <cuda_runtime.h>
#include <cuda_bf16.h>
#include <mma.h>
#include <math.h>
#include <stdint.h>

using namespace nvcuda;

// ---------------- problem constants ----------------
#define RESO 56
#define WS   7
#define CDIM 128
#define NHEAD 4
#define HDIM 32
#define HID  512
#define BATCH 32
#define NTOK (BATCH * RESO * RESO)      // 100352
#define NWIN (BATCH * 8 * 8)            // 2048 windows
#define TWIN 49

// ---------------- device scratch ----------------
__device__ float g_ln [(size_t)NTOK * CDIM];
__device__ float g_qkv[(size_t)NTOK * 3 * CDIM];
__device__ float g_o  [(size_t)NTOK * CDIM];
__device__ float g_x2 [(size_t)NTOK * CDIM];
__device__ float g_h1 [(size_t)NTOK * HID];
__device__ float g_wT [49152 + 16384 + 65536 + 65536];

__device__ __forceinline__ float f2tf32f(float f) {
    uint32_t r; asm("cvt.rna.tf32.f32 %0, %1;" : "=r"(r) : "f"(f));
    return __uint_as_float(r);
}
__device__ __forceinline__ uint32_t smem_u32(const void* p) {
    uint32_t a;
    asm("{ .reg .u64 t; cvta.to.shared.u64 t, %1; cvt.u32.u64 %0, t; }" : "=r"(a) : "l"(p));
    return a;
}
__device__ __forceinline__ void cp_async16(uint32_t saddr, const void* gaddr) {
    asm volatile("cp.async.ca.shared.global [%0], [%1], 16;" :: "r"(saddr), "l"(gaddr));
}
#define CP_COMMIT() asm volatile("cp.async.commit_group;" ::: "memory")
#define CP_WAIT(n)  asm volatile("cp.async.wait_group %0;" :: "n"(n) : "memory")

// ---------------- fused prep: weight rounding + LN1 ----------------
#define W_QKV_N 49152
#define W_PROJ_N 16384
#define W_W1_N 65536
#define W_W2_N 65536
#define W_TOTAL (W_QKV_N + W_PROJ_N + W_W1_N + W_W2_N)
#define W_BLOCKS ((W_TOTAL + 255) / 256)          // 769
#define LN_BLOCKS ((NTOK * 32) / 256)             // 12544

__global__ void prep_kernel(const float* __restrict__ w0, const float* __restrict__ w1,
                            const float* __restrict__ w2, const float* __restrict__ w3,
                            float* __restrict__ WT,
                            const float* __restrict__ x, const float* __restrict__ g,
                            const float* __restrict__ b, float* __restrict__ out)
{
    if (blockIdx.x < W_BLOCKS) {
        int idx = blockIdx.x * 256 + threadIdx.x;
        if (idx >= W_TOTAL) return;
        float v;
        if (idx < W_QKV_N)                          v = w0[idx];
        else if (idx < W_QKV_N + W_PROJ_N)          v = w1[idx - W_QKV_N];
        else if (idx < W_QKV_N + W_PROJ_N + W_W1_N) v = w2[idx - W_QKV_N - W_PROJ_N];
        else                                        v = w3[idx - W_QKV_N - W_PROJ_N - W_W1_N];
        WT[idx] = f2tf32f(v);
        return;
    }
    int gwarp = ((blockIdx.x - W_BLOCKS) * 256 + threadIdx.x) >> 5;
    int lane  = threadIdx.x & 31;
    if (gwarp >= NTOK) return;
    float4 v = ((const float4*)(x + (size_t)gwarp * CDIM))[lane];
    float s  = v.x + v.y + v.z + v.w;
    float ss = v.x*v.x + v.y*v.y + v.z*v.z + v.w*v.w;
    #pragma unroll
    for (int off = 16; off; off >>= 1) {
        s  += __shfl_xor_sync(0xffffffffu, s,  off);
        ss += __shfl_xor_sync(0xffffffffu, ss, off);
    }
    float mean = s * (1.0f / CDIM);
    float var  = ss * (1.0f / CDIM) - mean * mean;
    float rstd = rsqrtf(var + 1e-5f);
    float4 gg = ((const float4*)g)[lane];
    float4 bb = ((const float4*)b)[lane];
    float4 o;
    o.x = f2tf32f((v.x - mean) * rstd * gg.x + bb.x);
    o.y = f2tf32f((v.y - mean) * rstd * gg.y + bb.y);
    o.z = f2tf32f((v.z - mean) * rstd * gg.z + bb.z);
    o.w = f2tf32f((v.w - mean) * rstd * gg.w + bb.w);
    ((float4*)(out + (size_t)gwarp * CDIM))[lane] = o;
}

// ---------------- WMMA tf32 GEMM (unchanged from R5) ----------------------
enum { EPI_BIAS = 0, EPI_BIAS_RES = 1, EPI_GELU = 2, EPI_RES_LN2 = 3 };

#define A_STRIDE 36
#define B_STRIDE 136
#define C_STRIDE 132
#define ABUF (128 * A_STRIDE * 4)
#define BBUF (32 * B_STRIDE * 4)
#define SMEM_BYTES (2 * ABUF + 2 * BBUF)   // 71680 B

template <int EPI>
__global__ void __launch_bounds__(128, 2)
tc_gemm(const float* __restrict__ A, const float* __restrict__ B,
        const float* __restrict__ bias, const float* __restrict__ res,
        float* __restrict__ C, int N, int K,
        const float* __restrict__ lng, const float* __restrict__ lnb,
        float* __restrict__ C2)
{
    extern __shared__ char smem[];
    uint32_t sbase = smem_u32(smem);
    const int tid = threadIdx.x;
    const int wid = tid >> 5;
    const int warpM = wid & 1;
    const int warpN = wid >> 1;
    const int M0 = blockIdx.y * 128;
    const int N0 = blockIdx.x * 128;

    const float* Abase = A + (size_t)M0 * K;
    const float* Bbase = B + N0;
    const int nchunk = K >> 5;

    wmma::fragment<wmma::accumulator, 16, 16, 8, float> acc[4][4];
    #pragma unroll
    for (int i = 0; i < 4; i++)
        #pragma unroll
        for (int j = 0; j < 4; j++) wmma::fill_fragment(acc[i][j], 0.0f);

    auto load_chunk = [&](int c) {
        int buf = c & 1;
        uint32_t sa = sbase + buf * ABUF;
        uint32_t sb = sbase + 2 * ABUF + buf * BBUF;
        int k0 = c << 5;
        #pragma unroll
        for (int q = 0; q < 8; q++) {
            int e = tid + q * 128;
            int row = e >> 3, c16 = e & 7;
            cp_async16(sa + row * (A_STRIDE * 4) + c16 * 16,
                       Abase + (size_t)row * K + k0 + c16 * 4);
        }
        #pragma unroll
        for (int q = 0; q < 8; q++) {
            int e = tid + q * 128;
            int row = e >> 5, c16 = e & 31;
            cp_async16(sb + row * (B_STRIDE * 4) + c16 * 16,
                       Bbase + (size_t)(k0 + row) * N + c16 * 4);
        }
    };

    load_chunk(0);
    CP_COMMIT();

    for (int c = 0; c < nchunk; c++) {
        if (c + 1 < nchunk) {
            load_chunk(c + 1);
            CP_COMMIT();
            CP_WAIT(1);
        } else {
            CP_WAIT(0);
        }
        __syncthreads();

        int buf = c & 1;
        const float* As = (const float*)(smem + buf * ABUF);
        const float* Bs = (const float*)(smem + 2 * ABUF + buf * BBUF);
        #pragma unroll
        for (int ks = 0; ks < 4; ks++) {
            wmma::fragment<wmma::matrix_a, 16, 16, 8, wmma::precision::tf32, wmma::row_major> af[4];
            wmma::fragment<wmma::matrix_b, 16, 16, 8, wmma::precision::tf32, wmma::row_major> bf[4];
            #pragma unroll
            for (int i = 0; i < 4; i++)
                wmma::load_matrix_sync(af[i],
                    As + (warpM * 64 + i * 16) * A_STRIDE + ks * 8, A_STRIDE);
            #pragma unroll
            for (int j = 0; j < 4; j++)
                wmma::load_matrix_sync(bf[j],
                    Bs + (ks * 8) * B_STRIDE + warpN * 64 + j * 16, B_STRIDE);
            #pragma unroll
            for (int i = 0; i < 4; i++)
                #pragma unroll
                for (int j = 0; j < 4; j++)
                    wmma::mma_sync(acc[i][j], af[i], bf[j], acc[i][j]);
        }
        __syncthreads();
    }

    float* Cs = (float*)smem;
    #pragma unroll
    for (int i = 0; i < 4; i++)
        #pragma unroll
        for (int j = 0; j < 4; j++)
            wmma::store_matrix_sync(
                Cs + (warpM * 64 + i * 16) * C_STRIDE + warpN * 64 + j * 16,
                acc[i][j], C_STRIDE, wmma::mem_row_major);
    __syncthreads();

    #pragma unroll
    for (int e0 = 0; e0 < 32; e0++) {
        int e = tid + e0 * 128;
        int row = e >> 5;
        int c4  = (e & 31) * 4;
        size_t roff = (size_t)(M0 + row) * N + N0 + c4;
        float v[4];
        #pragma unroll
        for (int q = 0; q < 4; q++) {
            float t = Cs[row * C_STRIDE + c4 + q] + __ldg(bias + N0 + c4 + q);
            if (EPI == EPI_BIAS_RES || EPI == EPI_RES_LN2) t += res[roff + q];
            if (EPI == EPI_GELU) {
                t = 0.5f * t * (1.0f + erff(t * 0.70710678118654752f));
                t = f2tf32f(t);
            }
            v[q] = t;
        }
        if (EPI == EPI_RES_LN2) {
            float s  = v[0] + v[1] + v[2] + v[3];
            float ss = v[0]*v[0] + v[1]*v[1] + v[2]*v[2] + v[3]*v[3];
            #pragma unroll
            for (int off = 16; off; off >>= 1) {
                s  += __shfl_xor_sync(0xffffffffu, s,  off);
                ss += __shfl_xor_sync(0xffffffffu, ss, off);
            }
            float mean = s * (1.0f / CDIM);
            float var  = ss * (1.0f / CDIM) - mean * mean;
            float rstd = rsqrtf(var + 1e-5f);
            float lnv[4];
            #pragma unroll
            for (int q = 0; q < 4; q++)
                lnv[q] = f2tf32f((v[q] - mean) * rstd * __ldg(lng + c4 + q)
                                 + __ldg(lnb + c4 + q));
            *(float4*)(C2 + roff) = *(float4*)lnv;
        }
        *(float4*)(C + roff) = *(float4*)v;
    }
}

// ---------------- windowed attention: R4 mapping + float4 QK ----------
#define QS_STRIDE 36
#define S_STRIDE  50

__global__ __launch_bounds__(256)
void attn_kernel(const float* __restrict__ qkv, float* __restrict__ o)
{
    int blk  = blockIdx.x;
    int head = blk & 3;
    int w    = blk >> 2;
    int bimg = w >> 6;
    int win  = w & 63;
    int wr   = win >> 3, wc = win & 7;

    __shared__ int tok[TWIN];
    __shared__ __align__(16) float qs[52 * QS_STRIDE];
    __shared__ __align__(16) float ks[50 * QS_STRIDE];
    __shared__ __align__(16) float vs[49 * QS_STRIDE];
    __shared__ __align__(16) float S[52 * S_STRIDE];

    int tid = threadIdx.x;
    if (tid < TWIN) {
        int r = tid / WS, c = tid - r * WS;
        tok[tid] = bimg * (RESO * RESO) + (wr * WS + r) * RESO + (wc * WS + c);
    }
    // zero padding rows: qs rows 49..51, ks row 49
    if (tid < 3 * QS_STRIDE) qs[49 * QS_STRIDE + tid] = 0.0f;
    if (tid >= 128 && tid < 128 + QS_STRIDE) ks[49 * QS_STRIDE + (tid - 128)] = 0.0f;
    __syncthreads();

    for (int idx = tid; idx < TWIN * HDIM * 3; idx += 256) {
        int which = idx / (TWIN * HDIM);
        int rem   = idx - which * (TWIN * HDIM);
        int t = rem >> 5, d = rem & 31;
        float val = qkv[(size_t)tok[t] * (3 * CDIM) + which * CDIM + head * HDIM + d];
        float* dst = (which == 0) ? qs : (which == 1) ? ks : vs;
        dst[t * QS_STRIDE + d] = val;
    }
    __syncthreads();

    // S = q @ k^T * scale : 13 qi-groups(4) x 25 ki-groups(2), float4 d-blocks
    const float scale = 0.17677669529663687f;
    for (int t = tid; t < 13 * 25; t += 256) {
        int qg = t / 25, kg = t - qg * 25;
        int qi0 = qg * 4, ki0 = kg * 2;
        float a[4][2];
        #pragma unroll
        for (int i = 0; i < 4; i++) { a[i][0] = 0.0f; a[i][1] = 0.0f; }
        #pragma unroll
        for (int dq = 0; dq < 8; dq++) {
            float4 k0 = *(const float4*)&ks[ki0 * QS_STRIDE + 4 * dq];
            float4 k1 = *(const float4*)&ks[(ki0 + 1) * QS_STRIDE + 4 * dq];
            #pragma unroll
            for (int i = 0; i < 4; i++) {
                float4 q = *(const float4*)&qs[(qi0 + i) * QS_STRIDE + 4 * dq];
                a[i][0] = fmaf(q.x, k0.x, fmaf(q.y, k0.y, fmaf(q.z, k0.z, fmaf(q.w, k0.w, a[i][0]))));
                a[i][1] = fmaf(q.x, k1.x, fmaf(q.y, k1.y, fmaf(q.z, k1.z, fmaf(q.w, k1.w, a[i][1]))));
            }
        }
        #pragma unroll
        for (int i = 0; i < 4; i++)
            if (qi0 + i < TWIN)
                #pragma unroll
                for (int j = 0; j < 2; j++)
                    if (ki0 + j < TWIN)
                        S[(qi0 + i) * S_STRIDE + ki0 + j] = a[i][j] * scale;
    }
    __syncthreads();

    // softmax per row
    int warp = tid >> 5, lane = tid & 31;
    for (int row = warp; row < TWIN; row += 8) {
        float v0 = S[row * S_STRIDE + lane];
        float v1 = (lane + 32 < TWIN) ? S[row * S_STRIDE + lane + 32] : -3.4e38f;
        float m = fmaxf(v0, v1);
        #pragma unroll
        for (int off = 16; off; off >>= 1)
            m = fmaxf(m, __shfl_xor_sync(0xffffffffu, m, off));
        float e0 = __expf(v0 - m);
        float e1 = (lane + 32 < TWIN) ? __expf(v1 - m) : 0.0f;
        float s = e0 + e1;
        #pragma unroll
        for (int off = 16; off; off >>= 1)
            s += __shfl_xor_sync(0xffffffffu, s, off);
        float inv = 1.0f / s;
        S[row * S_STRIDE + lane] = e0 * inv;
        if (lane + 32 < TWIN) S[row * S_STRIDE + lane + 32] = e1 * inv;
    }
    __syncthreads();

    // O = P @ V : 13 qi-groups(4) x 16 d-pairs = 208 tiles
    for (int t = tid; t < 13 * 16; t += 256) {
        int qg = t / 16, dp = t - qg * 16;
        int qi0 = qg * 4, d = dp * 2;
        float ax0 = 0, ay0 = 0, ax1 = 0, ay1 = 0,
              ax2 = 0, ay2 = 0, ax3 = 0, ay3 = 0;
        for (int ki = 0; ki < TWIN; ki++) {
            float2 vv = *(const float2*)&vs[ki * QS_STRIDE + d];
            float s0 = S[(qi0 + 0) * S_STRIDE + ki];
            float s1 = S[(qi0 + 1) * S_STRIDE + ki];
            float s2 = S[(qi0 + 2) * S_STRIDE + ki];
            float s3 = S[(qi0 + 3) * S_STRIDE + ki];
            ax0 = fmaf(s0, vv.x, ax0); ay0 = fmaf(s0, vv.y, ay0);
            ax1 = fmaf(s1, vv.x, ax1); ay1 = fmaf(s1, vv.y, ay1);
            ax2 = fmaf(s2, vv.x, ax2); ay2 = fmaf(s2, vv.y, ay2);
            ax3 = fmaf(s3, vv.x, ax3); ay3 = fmaf(s3, vv.y, ay3);
        }
        float axs[4] = {ax0, ax1, ax2, ax3};
        float ays[4] = {ay0, ay1, ay2, ay3};
        #pragma unroll
        for (int i = 0; i < 4; i++) {
            if (qi0 + i < TWIN) {
                float* dst = o + (size_t)tok[qi0 + i] * CDIM + head * HDIM + d;
                dst[0] = f2tf32f(axs[i]);
                dst[1] = f2tf32f(ays[i]);
            }
        }
    }
}

// ---------------- launch ----------------
extern "C" void kernel_launch(void* const* d_in, const int* in_sizes, int n_in,
                              void* d_out, int out_size)
{
    const float* x      = (const float*)d_in[0];
    const float* ln1_g  = (const float*)d_in[1];
    const float* ln1_b  = (const float*)d_in[2];
    const float* qkv_w  = (const float*)d_in[3];
    const float* qkv_b  = (const float*)d_in[4];
    const float* proj_w = (const float*)d_in[5];
    const float* proj_b = (const float*)d_in[6];
    const float* ln2_g  = (const float*)d_in[7];
    const float* ln2_b  = (const float*)d_in[8];
    const float* mlp_w1 = (const float*)d_in[9];
    const float* mlp_b1 = (const float*)d_in[10];
    const float* mlp_w2 = (const float*)d_in[11];
    const float* mlp_b2 = (const float*)d_in[12];
    float* out = (float*)d_out;

    float *p_ln, *p_qkv, *p_o, *p_x2, *p_h1, *p_wT;
    cudaGetSymbolAddress((void**)&p_ln,  g_ln);
    cudaGetSymbolAddress((void**)&p_qkv, g_qkv);
    cudaGetSymbolAddress((void**)&p_o,   g_o);
    cudaGetSymbolAddress((void**)&p_x2,  g_x2);
    cudaGetSymbolAddress((void**)&p_h1,  g_h1);
    cudaGetSymbolAddress((void**)&p_wT,  g_wT);
    float* wt_qkv  = p_wT;
    float* wt_proj = p_wT + W_QKV_N;
    float* wt_w1   = p_wT + W_QKV_N + W_PROJ_N;
    float* wt_w2   = p_wT + W_QKV_N + W_PROJ_N + W_W1_N;

    cudaFuncSetAttribute(tc_gemm<EPI_BIAS>,     cudaFuncAttributeMaxDynamicSharedMemorySize, SMEM_BYTES);
    cudaFuncSetAttribute(tc_gemm<EPI_BIAS_RES>, cudaFuncAttributeMaxDynamicSharedMemorySize, SMEM_BYTES);
    cudaFuncSetAttribute(tc_gemm<EPI_GELU>,     cudaFuncAttributeMaxDynamicSharedMemorySize, SMEM_BYTES);
    cudaFuncSetAttribute(tc_gemm<EPI_RES_LN2>,  cudaFuncAttributeMaxDynamicSharedMemorySize, SMEM_BYTES);

    const int MT = NTOK / 128;  // 784

    // 0. fused prep: weight rounding + LN1
    prep_kernel<<<W_BLOCKS + LN_BLOCKS, 256>>>(qkv_w, proj_w, mlp_w1, mlp_w2, p_wT,
                                               x, ln1_g, ln1_b, p_ln);
    // 1. QKV = ln1 @ qkv_w + qkv_b
    tc_gemm<EPI_BIAS><<<dim3(3, MT), 128, SMEM_BYTES>>>(
        p_ln, wt_qkv, qkv_b, nullptr, p_qkv, 3 * CDIM, CDIM, nullptr, nullptr, nullptr);
    // 2. attention
    attn_kernel<<<NWIN * NHEAD, 256>>>(p_qkv, p_o);
    // 3. x2 = x + proj(o); fused LN2 -> p_ln
    tc_gemm<EPI_RES_LN2><<<dim3(1, MT), 128, SMEM_BYTES>>>(
        p_o, wt_proj, proj_b, x, p_x2, CDIM, CDIM, ln2_g, ln2_b, p_ln);
    // 4. h1 = gelu(ln2 @ w1 + b1)
    tc_gemm<EPI_GELU><<<dim3(4, MT), 128, SMEM_BYTES>>>(
        p_ln, wt_w1, mlp_b1, nullptr, p_h1, HID, CDIM, nullptr, nullptr, nullptr);
    // 5. out = x2 + h1 @ w2 + b2
    tc_gemm<EPI_BIAS_RES><<<dim3(1, MT), 128, SMEM_BYTES>>>(
        p_h1, wt_w2, mlp_b2, p_x2, out, CDIM, HID, nullptr, nullptr, nullptr);
}